// round 3
// baseline (speedup 1.0000x reference)
#include <cuda_runtime.h>

#define B_    8
#define CI_   512
#define CO_   256
#define HW_   64
#define YP_   136      // padded y stride (y rows -1..130 live at 0..131; valid y r at r+1)
#define ZS_   128
#define COT   4        // output channels per block
#define CIT   4        // input channels per smem chunk
#define QT    13       // quad columns per block
#define NQ    5        // quads per thread (vertical strip): 13*5 = 65 rows exact
#define NTH   169

__device__ float g_km[CI_ * 9 * CO_];          // modulated, flipped: [ci][tap][co]
__device__ float g_y[B_ * CO_ * YP_ * YP_];    // padded intermediate (pad stays 0)

__device__ __forceinline__ void ffma2(unsigned long long& d, unsigned long long a, unsigned long long b) {
    asm("fma.rn.f32x2 %0, %1, %2, %0;" : "+l"(d) : "l"(a), "l"(b));
}
__device__ __forceinline__ float f2lo(unsigned long long v) { return __uint_as_float((unsigned)v); }
__device__ __forceinline__ float f2hi(unsigned long long v) { return __uint_as_float((unsigned)(v >> 32)); }

// ---------------- prep: demodulate + flip weights, layout [ci][tap][co] ----------------
__global__ void prep_kernel(const float* __restrict__ w) {
    __shared__ float red[256];
    const int o = blockIdx.x, tid = threadIdx.x;
    const float wsc = 1.0f / sqrtf((float)(CI_ * 9));
    const float* wo = w + o * (CI_ * 9);
    float s = 0.f;
    for (int idx = tid; idx < CI_ * 9; idx += 256) {
        float v = wo[idx] * wsc;
        s += v * v;
    }
    red[tid] = s;
    __syncthreads();
    for (int st = 128; st > 0; st >>= 1) {
        if (tid < st) red[tid] += red[tid + st];
        __syncthreads();
    }
    const float scale = wsc * rsqrtf(red[0] + 1e-6f);
    for (int idx = tid; idx < CI_ * 9; idx += 256) {
        int i = idx / 9, t = idx % 9, kh = t / 3, kw = t % 3;
        float v = wo[i * 9 + (2 - kh) * 3 + (2 - kw)] * scale;   // spatial flip
        g_km[idx * CO_ + o] = v;                                 // idx == i*9+t
    }
}

// ---------------- transposed conv, quad-decomposed, 5-quad vertical register blocking ----------------
// tap -> (x row sel, x col sel, pixel):
//   t0:(0,0)p0  t1:(0,1)p1  t2:(0,1)p0  t3:(1,0)p2  t4:(1,1)p3
//   t5:(1,1)p2  t6:(1,0)p0  t7:(1,1)p1  t8:(1,1)p0
__global__ void __launch_bounds__(NTH, 2) conv_kernel(const float* __restrict__ x, int co_base) {
    __shared__ float2 xs[CIT][67][14];          // x tile, duplicated (v,v) for f32x2
    __shared__ ulonglong2 wsm[CIT][9];          // 4 co per (ci,tap): pairs (c0,c1),(c2,c3)

    const int tid = threadIdx.x;
    const int bb   = blockIdx.z >> 5;           // batch
    const int tile = blockIdx.z & 31;
    const int co0  = co_base + tile * COT;
    const int B0   = blockIdx.x * QT;
    const int qy   = tid / QT;                  // 0..12 -> quad rows 5qy..5qy+4
    const int qx   = tid % QT;

    unsigned long long acc[NQ][4][2];           // [quad][pixel][co-pair]
#pragma unroll
    for (int q = 0; q < NQ; q++)
#pragma unroll
        for (int p = 0; p < 4; p++) { acc[q][p][0] = 0ull; acc[q][p][1] = 0ull; }

    const float* xb = x + (size_t)bb * CI_ * HW_ * HW_;
    float* wsf = (float*)wsm;

    constexpr int RI[9] = {0,0,0,1,1,1,1,1,1};
    constexpr int CJ[9] = {0,1,1,0,1,1,0,1,1};
    constexpr int PP[9] = {0,1,0,2,3,2,0,1,0};

    for (int cc = 0; cc < CI_; cc += CIT) {
        __syncthreads();
        // stage x tile: rows -1..65 (67), cols B0-1..B0+12 (14)
        for (int idx = tid; idx < CIT * 67 * 14; idx += NTH) {
            int ci = idx / (67 * 14), rem = idx % (67 * 14), r = rem / 14, c = rem % 14;
            int iy = r - 1, ix = B0 - 1 + c;
            float v = 0.f;
            if ((unsigned)iy < HW_ && (unsigned)ix < HW_)
                v = xb[((cc + ci) * HW_ + iy) * HW_ + ix];
            xs[ci][r][c] = make_float2(v, v);
        }
        // stage weights
        for (int idx = tid; idx < CIT * 9 * COT; idx += NTH) {
            int ci = idx / (9 * COT), rem = idx % (9 * COT), t = rem / COT, c = rem % COT;
            wsf[idx] = g_km[((cc + ci) * 9 + t) * CO_ + co0 + c];
        }
        __syncthreads();
#pragma unroll
        for (int ci = 0; ci < CIT; ci++) {
            unsigned long long xr[NQ + 1][2];
#pragma unroll
            for (int i = 0; i <= NQ; i++) {
                xr[i][0] = *(const unsigned long long*)&xs[ci][NQ * qy + i][qx];
                xr[i][1] = *(const unsigned long long*)&xs[ci][NQ * qy + i][qx + 1];
            }
#pragma unroll
            for (int t = 0; t < 9; t++) {
                ulonglong2 kk = wsm[ci][t];
#pragma unroll
                for (int q = 0; q < NQ; q++) {
                    unsigned long long xv = xr[q + RI[t]][CJ[t]];
                    ffma2(acc[q][PP[t]][0], xv, kk.x);
                    ffma2(acc[q][PP[t]][1], xv, kk.y);
                }
            }
        }
    }

    // epilogue: write padded y
    const int a0 = NQ * qy;
    const int ox = 2 * (B0 + qx);
    const bool c1 = ox < 128;
    float* ybase = g_y + (size_t)(bb * CO_ + co0) * (YP_ * YP_);
#pragma unroll
    for (int q = 0; q < NQ; q++) {
        const int oy = 2 * (a0 + q);
        const bool r1 = oy < 128;
        const size_t base = (size_t)(oy + 1) * YP_ + (ox + 1);
#pragma unroll
        for (int j = 0; j < 2; j++)
#pragma unroll
            for (int h = 0; h < 2; h++) {
                float* yco = ybase + (size_t)(2 * j + h) * (YP_ * YP_);
                float v0 = h ? f2hi(acc[q][0][j]) : f2lo(acc[q][0][j]);
                float v1 = h ? f2hi(acc[q][1][j]) : f2lo(acc[q][1][j]);
                float v2 = h ? f2hi(acc[q][2][j]) : f2lo(acc[q][2][j]);
                float v3 = h ? f2hi(acc[q][3][j]) : f2lo(acc[q][3][j]);
                yco[base] = v0;
                if (c1) yco[base + 1] = v1;
                if (r1) yco[base + YP_] = v2;
                if (r1 && c1) yco[base + YP_ + 1] = v3;
            }
    }
}

// ---------------- depthwise 4x4 FIR blur, separable row-streaming ----------------
__global__ void blur_kernel(float* __restrict__ z, int co_base) {
    const int cx = threadIdx.x;                  // 0..31 -> out cols 4cx..4cx+3
    const int ry = threadIdx.y;                  // 0..7  -> out rows 16ry..16ry+15
    const int bc = blockIdx.z;
    const int b = bc >> 7;
    const int col = co_base + (bc & 127);
    const float* yb = g_y + (size_t)(b * CO_ + col) * (YP_ * YP_);
    float* zb = z + (size_t)(b * CO_ + col) * (ZS_ * ZS_);
    const int c0 = cx * 4;
    const int zy0 = ry * 16;

    float4 h0 = {}, h1 = {}, h2 = {};
#pragma unroll
    for (int k = 0; k < 19; k++) {
        const float* row = yb + (size_t)(zy0 + k) * YP_ + c0;
        float4 a = *(const float4*)row;
        float4 e = *(const float4*)(row + 4);
        float4 h;
        h.x = a.x + 3.f * a.y + 3.f * a.z + a.w;
        h.y = a.y + 3.f * a.z + 3.f * a.w + e.x;
        h.z = a.z + 3.f * a.w + 3.f * e.x + e.y;
        h.w = a.w + 3.f * e.x + 3.f * e.y + e.z;
        if (k >= 3) {
            float4 o;
            o.x = (h0.x + 3.f * h1.x + 3.f * h2.x + h.x) * 0.0625f;
            o.y = (h0.y + 3.f * h1.y + 3.f * h2.y + h.y) * 0.0625f;
            o.z = (h0.z + 3.f * h1.z + 3.f * h2.z + h.z) * 0.0625f;
            o.w = (h0.w + 3.f * h1.w + 3.f * h2.w + h.w) * 0.0625f;
            *(float4*)&zb[(size_t)(zy0 + k - 3) * ZS_ + c0] = o;
        }
        h0 = h1; h1 = h2; h2 = h;
    }
}

extern "C" void kernel_launch(void* const* d_in, const int* in_sizes, int n_in,
                              void* d_out, int out_size) {
    const float* x = (const float*)d_in[0];
    const float* w = (const float*)d_in[1];
    float* z = (float*)d_out;
    prep_kernel<<<CO_, 256>>>(w);
    conv_kernel<<<dim3(5, 1, B_ * 32), NTH>>>(x, 0);      // co 0..127
    blur_kernel<<<dim3(1, 1, B_ * 128), dim3(32, 8)>>>(z, 0);
    conv_kernel<<<dim3(5, 1, B_ * 32), NTH>>>(x, 128);    // co 128..255 (ncu position 3)
    blur_kernel<<<dim3(1, 1, B_ * 128), dim3(32, 8)>>>(z, 128);
}

// round 8
// speedup vs baseline: 7.3838x; 7.3838x over previous
#include <cuda_runtime.h>
#include <cstdint>

#define B_    8
#define CI_   512
#define CO_   256
#define HW_   64
#define YP_   136
#define YPP   (YP_ * YP_)
#define ZS_   128
#define NQUAD 65
#define NQ2   (NQUAD * NQUAD)                 // 4225
#define NTOT  (B_ * NQ2)                      // 33800 quads
#define MT_   128                             // M per CTA
#define NTILES ((NTOT + MT_ - 1) / MT_)       // 265

__device__ float g_wf[9 * 16 * 4 * 4 * 32 * 16];   // B frag layout: [tap][ch][kt][wn][lane][nt*2+reg]
__device__ float g_xr[B_ * CI_ * HW_ * HW_];       // tf32-rounded x copy
__device__ float g_y[B_ * CO_ * YPP];              // padded intermediate (pad stays 0)

__device__ __forceinline__ uint32_t f2tf32(float f) {   // RN-to-even tf32 bits
    uint32_t u = __float_as_uint(f);
    u = u + 0xFFFu + ((u >> 13) & 1u);
    return u & 0xFFFFE000u;
}

// D(16x8) += A(16x8) * B(8x8), tf32. a packed as (v0,v1,v2,v3)=((m,k),(m,k+4),(m+8,k),(m+8,k+4))
__device__ __forceinline__ void mma8(float* c, float4 a, float b0, float b1) {
    asm volatile(
        "mma.sync.aligned.m16n8k8.row.col.f32.tf32.tf32.f32 "
        "{%0,%1,%2,%3}, {%4,%5,%6,%7}, {%8,%9}, {%0,%1,%2,%3};"
        : "+f"(c[0]), "+f"(c[1]), "+f"(c[2]), "+f"(c[3])
        : "r"(__float_as_uint(a.x)), "r"(__float_as_uint(a.z)),
          "r"(__float_as_uint(a.y)), "r"(__float_as_uint(a.w)),
          "r"(__float_as_uint(b0)), "r"(__float_as_uint(b1)));
}

// ---------------- parity tables as constexpr functions (compile-time folded) ----------------
// shifts S = RI*2+CJ; parity p taps: p0:{0,2,6,8}->S{0,1,2,3}, p1:{1,7}->S{1,3},
//                                    p2:{3,5}->S{2,3}, p3:{4}->S{3}
__host__ __device__ constexpr int pc_nt(int P) { return P == 0 ? 4 : (P == 3 ? 1 : 2); }
__host__ __device__ constexpr int pc_sh(int P, int j) {
    return P == 0 ? j
         : P == 1 ? (j == 0 ? 1 : 3)
         : P == 2 ? (j == 0 ? 2 : 3)
         : 3;
}
__host__ __device__ constexpr int pc_tp(int P, int j) {
    return P == 0 ? (j == 0 ? 0 : j == 1 ? 2 : j == 2 ? 6 : 8)
         : P == 1 ? (j == 0 ? 1 : 7)
         : P == 2 ? (j == 0 ? 3 : 5)
         : 4;
}

// ---------------- x -> tf32-rounded copy ----------------
__global__ void roundx_kernel(const float* __restrict__ x) {
    int i = blockIdx.x * 256 + threadIdx.x;
    float4 v = ((const float4*)x)[i];
    uint4 u;
    u.x = f2tf32(v.x); u.y = f2tf32(v.y); u.z = f2tf32(v.z); u.w = f2tf32(v.w);
    ((uint4*)g_xr)[i] = u;
}

// ---------------- prep: demodulate + flip + tf32-round, B fragment layout ----------------
__global__ void prep_kernel(const float* __restrict__ w) {
    __shared__ float red[256];
    const int o = blockIdx.x, tid = threadIdx.x;
    const float wsc = 1.0f / sqrtf((float)(CI_ * 9));
    const float* wo = w + o * (CI_ * 9);
    float s = 0.f;
    for (int idx = tid; idx < CI_ * 9; idx += 256) {
        float v = wo[idx] * wsc;
        s += v * v;
    }
    red[tid] = s;
    __syncthreads();
    for (int st = 128; st > 0; st >>= 1) {
        if (tid < st) red[tid] += red[tid + st];
        __syncthreads();
    }
    const float scale = wsc * rsqrtf(red[0] + 1e-6f);
    const int wn = o >> 6, c6 = o & 63, nt = c6 >> 3, cn = c6 & 7;
    for (int idx = tid; idx < CI_ * 9; idx += 256) {
        int i = idx / 9, t = idx % 9, kh = t / 3, kw = t % 3;
        float v = wo[i * 9 + (2 - kh) * 3 + (2 - kw)] * scale;       // spatial flip
        int ch = i >> 5, k5 = i & 31, kt = k5 >> 3, ck = k5 & 7;
        int lane = cn * 4 + (ck & 3), reg = ck >> 2;
        g_wf[(size_t)((((t * 16 + ch) * 4 + kt) * 4 + wn) * 32 + lane) * 16 + nt * 2 + reg]
            = __uint_as_float(f2tf32(v));
    }
}

// ---------------- transposed conv, one parity, TF32 mma.sync ----------------
template <int P>
__global__ void __launch_bounds__(256, 1) conv_mma() {
    constexpr int NT = pc_nt(P);
    extern __shared__ float4 smA[];            // NT tiles x 1024 float4 frag entries

    const int tid = threadIdx.x, lane = tid & 31, warp = tid >> 5;
    const int wm = warp >> 2, wn = warp & 3;
    const int nt0 = blockIdx.x * MT_;

    // ---- staging precompute: per (i, row, shift) base element offsets + validity ----
    uint32_t base[4][2][NT];
    uint32_t vmask = 0;
    int kOff0[4], eIdx[4];
#pragma unroll
    for (int i = 0; i < 4; i++) {
        const int e = tid + i * 256;
        const int mtkt = e >> 5, sl = e & 31;
        eIdx[i]  = e;
        kOff0[i] = ((mtkt & 3) * 8 + (sl & 3)) << 12;          // kl * 4096
        const int m0 = (mtkt >> 2) * 16 + (sl >> 2);
#pragma unroll
        for (int row = 0; row < 2; row++) {
            const int gm = nt0 + m0 + row * 8;
            const int b = gm / NQ2, r = gm - b * NQ2;
            const int qa = r / NQUAD, qb = r - qa * NQUAD;
            const bool mok = gm < NTOT;
#pragma unroll
            for (int s = 0; s < NT; s++) {
                const int sh = pc_sh(P, s);
                const int iy = qa - 1 + (sh >> 1), ix = qb - 1 + (sh & 1);
                base[i][row][s] = (uint32_t)((b * CI_) << 12) + (uint32_t)(iy * HW_ + ix);
                if (mok && (unsigned)iy < HW_ && (unsigned)ix < HW_)
                    vmask |= 1u << ((i * 2 + row) * NT + s);
            }
        }
    }

    float acc[4][8][4];
#pragma unroll
    for (int q = 0; q < 4; q++)
#pragma unroll
        for (int n = 0; n < 8; n++)
#pragma unroll
            for (int r = 0; r < 4; r++) acc[q][n][r] = 0.f;

    for (int ch = 0; ch < 16; ch++) {
        const uint32_t cco = (uint32_t)ch << 17;               // ch*32*4096
        if (ch) __syncthreads();                               // mma reads done before overwrite
        // ---- stage A: frag-entry STS.128, loads from tf32-rounded x ----
#pragma unroll
        for (int i = 0; i < 4; i++) {
            const uint32_t k0 = cco + kOff0[i];
            const uint32_t k1 = k0 + (4u << 12);
#pragma unroll
            for (int s = 0; s < NT; s++) {
                float4 v;
                v.x = (vmask >> ((i * 2 + 0) * NT + s) & 1) ? g_xr[base[i][0][s] + k0] : 0.f;
                v.y = (vmask >> ((i * 2 + 0) * NT + s) & 1) ? g_xr[base[i][0][s] + k1] : 0.f;
                v.z = (vmask >> ((i * 2 + 1) * NT + s) & 1) ? g_xr[base[i][1][s] + k0] : 0.f;
                v.w = (vmask >> ((i * 2 + 1) * NT + s) & 1) ? g_xr[base[i][1][s] + k1] : 0.f;
                smA[s * 1024 + eIdx[i]] = v;
            }
        }
        __syncthreads();
        // ---- compute ----
#pragma unroll
        for (int j = 0; j < NT; j++) {
            const int tap = pc_tp(P, j);
#pragma unroll
            for (int kt = 0; kt < 4; kt++) {
                float4 af[4];
#pragma unroll
                for (int q = 0; q < 4; q++)
                    af[q] = smA[j * 1024 + ((wm * 4 + q) * 4 + kt) * 32 + lane];
                const float4* bp = (const float4*)&g_wf[
                    (size_t)((((tap * 16 + ch) * 4 + kt) * 4 + wn) * 32 + lane) * 16];
                float4 bf0 = bp[0], bf1 = bp[1], bf2 = bp[2], bf3 = bp[3];
#pragma unroll
                for (int q = 0; q < 4; q++) {
                    mma8(acc[q][0], af[q], bf0.x, bf0.y);
                    mma8(acc[q][1], af[q], bf0.z, bf0.w);
                    mma8(acc[q][2], af[q], bf1.x, bf1.y);
                    mma8(acc[q][3], af[q], bf1.z, bf1.w);
                    mma8(acc[q][4], af[q], bf2.x, bf2.y);
                    mma8(acc[q][5], af[q], bf2.z, bf2.w);
                    mma8(acc[q][6], af[q], bf3.x, bf3.y);
                    mma8(acc[q][7], af[q], bf3.z, bf3.w);
                }
            }
        }
    }

    // ---- epilogue: C frag -> g_y (parity pixel per quad) ----
#pragma unroll
    for (int q = 0; q < 4; q++) {
        size_t addr[2]; bool ok[2];
#pragma unroll
        for (int row = 0; row < 2; row++) {
            const int gm = nt0 + wm * 64 + q * 16 + (lane >> 2) + row * 8;
            const int b = gm / NQ2, r = gm - b * NQ2;
            const int qa = r / NQUAD, qb = r - qa * NQUAD;
            const int oy = 2 * qa + (P >> 1), ox = 2 * qb + (P & 1);
            ok[row] = (gm < NTOT) && (oy <= 128) && (ox <= 128);
            addr[row] = (size_t)(b * CO_) * YPP + (size_t)(oy + 1) * YP_ + (ox + 1);
        }
#pragma unroll
        for (int n = 0; n < 8; n++) {
            const int co = wn * 64 + n * 8 + 2 * (lane & 3);
            if (ok[0]) {
                size_t a0 = addr[0] + (size_t)co * YPP;
                g_y[a0] = acc[q][n][0];
                g_y[a0 + YPP] = acc[q][n][1];
            }
            if (ok[1]) {
                size_t a1 = addr[1] + (size_t)co * YPP;
                g_y[a1] = acc[q][n][2];
                g_y[a1 + YPP] = acc[q][n][3];
            }
        }
    }
}

// ---------------- depthwise 4x4 FIR blur, separable row-streaming ----------------
__global__ void blur_kernel(float* __restrict__ z) {
    const int cx = threadIdx.x;
    const int ry = threadIdx.y;
    const int bc = blockIdx.z;
    const int b = bc >> 8;
    const int col = bc & 255;
    const float* yb = g_y + (size_t)(b * CO_ + col) * YPP;
    float* zb = z + (size_t)(b * CO_ + col) * (ZS_ * ZS_);
    const int c0 = cx * 4;
    const int zy0 = ry * 16;

    float4 h0 = {}, h1 = {}, h2 = {};
#pragma unroll
    for (int k = 0; k < 19; k++) {
        const float* row = yb + (size_t)(zy0 + k) * YP_ + c0;
        float4 a = *(const float4*)row;
        float4 e = *(const float4*)(row + 4);
        float4 h;
        h.x = a.x + 3.f * a.y + 3.f * a.z + a.w;
        h.y = a.y + 3.f * a.z + 3.f * a.w + e.x;
        h.z = a.z + 3.f * a.w + 3.f * e.x + e.y;
        h.w = a.w + 3.f * e.x + 3.f * e.y + e.z;
        if (k >= 3) {
            float4 o;
            o.x = (h0.x + 3.f * h1.x + 3.f * h2.x + h.x) * 0.0625f;
            o.y = (h0.y + 3.f * h1.y + 3.f * h2.y + h.y) * 0.0625f;
            o.z = (h0.z + 3.f * h1.z + 3.f * h2.z + h.z) * 0.0625f;
            o.w = (h0.w + 3.f * h1.w + 3.f * h2.w + h.w) * 0.0625f;
            *(float4*)&zb[(size_t)(zy0 + k - 3) * ZS_ + c0] = o;
        }
        h0 = h1; h1 = h2; h2 = h;
    }
}

extern "C" void kernel_launch(void* const* d_in, const int* in_sizes, int n_in,
                              void* d_out, int out_size) {
    const float* x = (const float*)d_in[0];
    const float* w = (const float*)d_in[1];
    float* z = (float*)d_out;
    cudaFuncSetAttribute(conv_mma<0>, cudaFuncAttributeMaxDynamicSharedMemorySize, 4 * 16384);
    cudaFuncSetAttribute(conv_mma<1>, cudaFuncAttributeMaxDynamicSharedMemorySize, 2 * 16384);
    cudaFuncSetAttribute(conv_mma<2>, cudaFuncAttributeMaxDynamicSharedMemorySize, 2 * 16384);
    cudaFuncSetAttribute(conv_mma<3>, cudaFuncAttributeMaxDynamicSharedMemorySize, 1 * 16384);
    roundx_kernel<<<16384, 256>>>(x);
    prep_kernel<<<CO_, 256>>>(w);
    conv_mma<3><<<NTILES, 256, 1 * 16384>>>();
    conv_mma<0><<<NTILES, 256, 4 * 16384>>>();
    conv_mma<1><<<NTILES, 256, 2 * 16384>>>();
    conv_mma<2><<<NTILES, 256, 2 * 16384>>>();
    blur_kernel<<<dim3(1, 1, B_ * CO_), dim3(32, 8)>>>(z);
}